// round 4
// baseline (speedup 1.0000x reference)
#include <cuda_runtime.h>
#include <math.h>

#define BB 256
#define NCH 32
#define TT 2000
#define NTF 4
#define NSF 40
#define NSUB 20
#define TK 25
#define NCLS 4
#define NPAIR 210
#define NCHUNK 4
#define TC 500           // 4*500 = 2000
#define XS_STRIDE 524    // TC + 24 halo, multiple of 4 (16B alignment)
#define YS_STRIDE 504    // TC + 4 pad, multiple of 4 (16B alignment)
#define NSWEEP 6

typedef unsigned long long ull;

// Scratch: projected weights + per-chunk partial sums (full 20x20 + 20 means).
__device__ float g_Wc[128 * 20];               // [(g*32+c)*20 + s]
__device__ float g_part[NCHUNK][BB][420];      // [0..399]=sum y_i y_j (full), [400..419]=sum y_i

// ---- packed fp32x2 helpers (FFMA2: 2x fp32 FMA density on sm_103a) ----
__device__ __forceinline__ void fma2(ull& d, ull a, ull b) {
    asm("fma.rn.f32x2 %0, %1, %2, %0;" : "+l"(d) : "l"(a), "l"(b));
}
__device__ __forceinline__ ull pack2(float lo, float hi) {
    ull r; asm("mov.b64 %0, {%1, %2};" : "=l"(r) : "f"(lo), "f"(hi)); return r;
}
__device__ __forceinline__ float2 unpack2(ull v) {
    float2 f; asm("mov.b64 {%0, %1}, %2;" : "=f"(f.x), "=f"(f.y) : "l"(v)); return f;
}

// ---------------------------------------------------------------------------
// Wc[s,g,c] = sum_f W_bimap[s,f] * conv2_w[f,g,c]  (biases cancel in cov)
// ---------------------------------------------------------------------------
__global__ void prep_kernel(const float* __restrict__ conv2_w,
                            const float* __restrict__ W_bimap) {
    int idx = blockIdx.x * blockDim.x + threadIdx.x;
    if (idx < 128 * 20) {
        int s = idx % 20, gc = idx / 20;
        float acc = 0.f;
        #pragma unroll 8
        for (int f = 0; f < NSF; ++f)
            acc += W_bimap[s * NSF + f] * conv2_w[f * 128 + gc];
        g_Wc[gc * 20 + s] = acc;
    }
}

// ---------------------------------------------------------------------------
// Fused conv1 (reflect pad) -> 20-dim projection -> tiled covariance partials.
// One block per (chunk, batch); each thread produces 4 consecutive t.
// ---------------------------------------------------------------------------
__global__ void __launch_bounds__(128, 1)
conv_cov_kernel(const float* __restrict__ x, const float* __restrict__ w1) {
    extern __shared__ float smem[];
    float* xs  = smem;                      // 32 * 524
    float* ys  = xs + NCH * XS_STRIDE;      // 20 * 504
    float* wcs = ys + 20 * YS_STRIDE;       // 2560
    float* w2p = wcs + 2560;                // 8 slots * 28 floats = 224

    const int tid = threadIdx.x;
    const int chunk = blockIdx.x, b = blockIdx.y;
    const int t0 = chunk * TC;

    // x tile with 12/12 reflect halo
    const float* xb = x + (size_t)b * NCH * TT;
    for (int idx = tid; idx < NCH * (TC + 24); idx += 128) {
        int c = idx / (TC + 24), tt = idx % (TC + 24);
        int gi = t0 + tt - 12;
        if (gi < 0) gi = -gi;
        if (gi >= TT) gi = 2 * TT - 2 - gi;
        xs[c * XS_STRIDE + tt] = xb[c * TT + gi];
    }
    for (int idx = tid; idx < 2560; idx += 128) wcs[idx] = g_Wc[idx];
    // packed conv1 weights: slot = phase*4+g, 13 pairs + 1 zero pad (28 floats)
    //  phase A (even t): pair i = (w[2i], w[2i+1]), i=12 -> (w[24], 0)
    //  phase B (odd t) : pair i = (w[2i-1], w[2i]), i=0 -> (0, w[0])
    if (tid < 104) {
        int phase = tid / 52, rem = tid % 52, g = rem / 13, i = rem % 13;
        float lo, hi;
        if (phase == 0) {
            lo = w1[g * TK + 2 * i];
            hi = (i < 12) ? w1[g * TK + 2 * i + 1] : 0.f;
        } else {
            lo = (i == 0) ? 0.f : w1[g * TK + 2 * i - 1];
            hi = w1[g * TK + 2 * i];
        }
        int base = (phase * 4 + g) * 28 + 2 * i;
        w2p[base] = lo; w2p[base + 1] = hi;
    }
    if (tid >= 104 && tid < 120) {          // zero the pads
        int s = tid - 104;                  // 0..15 -> 8 slots x 2 floats
        w2p[(s >> 1) * 28 + 26 + (s & 1)] = 0.f;
    }
    __syncthreads();

    // ---- main conv + projection: thread tid -> t = tl..tl+3 ----
    if (tid < 125) {
        const int tl = 4 * tid;
        ull accA[10], accB[10], accC[10], accD[10];
        #pragma unroll
        for (int q = 0; q < 10; ++q) { accA[q]=0; accB[q]=0; accC[q]=0; accD[q]=0; }

        const ull* w2 = (const ull*)w2p;    // [slot*14 + i]

        #pragma unroll
        for (int g = 0; g < NTF; ++g) {
            ull wA[13], wB[13];
            #pragma unroll
            for (int i = 0; i < 13; ++i) {
                wA[i] = w2[g * 14 + i];
                wB[i] = w2[(4 + g) * 14 + i];
            }
            for (int c = 0; c < NCH; ++c) {
                const ull* xr = (const ull*)&xs[c * XS_STRIDE + tl];  // 16B aligned
                ull win[14];
                #pragma unroll
                for (int i = 0; i < 14; ++i) win[i] = xr[i];

                ull sA = 0, sB = 0, sC = 0, sD = 0;
                #pragma unroll
                for (int i = 0; i < 13; ++i) {
                    fma2(sA, win[i],     wA[i]);   // h1[g,c,tl]
                    fma2(sB, win[i],     wB[i]);   // h1[g,c,tl+1]
                    fma2(sC, win[i + 1], wA[i]);   // h1[g,c,tl+2]
                    fma2(sD, win[i + 1], wB[i]);   // h1[g,c,tl+3]
                }
                float2 fa = unpack2(sA), fb = unpack2(sB);
                float2 fc = unpack2(sC), fd = unpack2(sD);
                ull pa = pack2(fa.x + fa.y, fa.x + fa.y);
                ull pb = pack2(fb.x + fb.y, fb.x + fb.y);
                ull pc = pack2(fc.x + fc.y, fc.x + fc.y);
                ull pd = pack2(fd.x + fd.y, fd.x + fd.y);
                const ull* wv = (const ull*)&wcs[(g * 32 + c) * 20];  // 16B aligned
                #pragma unroll
                for (int q = 0; q < 10; ++q) {
                    ull w = wv[q];
                    fma2(accA[q], w, pa);
                    fma2(accB[q], w, pb);
                    fma2(accC[q], w, pc);
                    fma2(accD[q], w, pd);
                }
            }
        }
        // transpose-store: row s gets (t0..t3) contiguously -> STS.128
        #pragma unroll
        for (int q = 0; q < 10; ++q) {
            float2 a = unpack2(accA[q]), bb2 = unpack2(accB[q]);
            float2 cc = unpack2(accC[q]), dd = unpack2(accD[q]);
            *(float4*)&ys[(2 * q)     * YS_STRIDE + tl] = make_float4(a.x, bb2.x, cc.x, dd.x);
            *(float4*)&ys[(2 * q + 1) * YS_STRIDE + tl] = make_float4(a.y, bb2.y, cc.y, dd.y);
        }
    }
    __syncthreads();

    // ---- tiled covariance: 25 threads compute full 20x20 in 4x4 tiles ----
    if (tid < 25) {
        const int i0 = (tid / 5) * 4, j0 = (tid % 5) * 4;
        ull acc[16];
        #pragma unroll
        for (int e = 0; e < 16; ++e) acc[e] = 0;
        for (int t4 = 0; t4 < TC / 4; ++t4) {
            ull ri[4][2], rj[4][2];
            #pragma unroll
            for (int a = 0; a < 4; ++a) {
                const ull* pi = (const ull*)&ys[(i0 + a) * YS_STRIDE + 4 * t4];
                const ull* pj = (const ull*)&ys[(j0 + a) * YS_STRIDE + 4 * t4];
                ri[a][0] = pi[0]; ri[a][1] = pi[1];
                rj[a][0] = pj[0]; rj[a][1] = pj[1];
            }
            #pragma unroll
            for (int a = 0; a < 4; ++a)
                #pragma unroll
                for (int d = 0; d < 4; ++d) {
                    fma2(acc[a * 4 + d], ri[a][0], rj[d][0]);
                    fma2(acc[a * 4 + d], ri[a][1], rj[d][1]);
                }
        }
        #pragma unroll
        for (int a = 0; a < 4; ++a)
            #pragma unroll
            for (int d = 0; d < 4; ++d) {
                float2 f = unpack2(acc[a * 4 + d]);
                g_part[chunk][b][(i0 + a) * 20 + (j0 + d)] = f.x + f.y;
            }
    } else if (tid >= 32 && tid < 52) {
        const int r = tid - 32;
        const ull ones = pack2(1.f, 1.f);
        ull acc = 0;
        const ull* pr = (const ull*)&ys[r * YS_STRIDE];
        for (int t2 = 0; t2 < TC / 2; ++t2) fma2(acc, pr[t2], ones);
        float2 f = unpack2(acc);
        g_part[chunk][b][400 + r] = f.x + f.y;
    }
}

// ---------------------------------------------------------------------------
// Per-batch: assemble S, parallel-order Jacobi, matrix log, classifier.
// ---------------------------------------------------------------------------
__global__ void eig_kernel(const float* __restrict__ clf_w,
                           const float* __restrict__ clf_b,
                           float* __restrict__ out) {
    __shared__ float S[20][21];
    __shared__ float U[20][21];
    __shared__ float m[20], lw[20];
    __shared__ float cs[10], sn[10];
    __shared__ int   pa[10], qa[10];

    const int lane = threadIdx.x;
    const int b = blockIdx.x;

    if (lane < 20) {
        float acc = 0.f;
        #pragma unroll
        for (int ch = 0; ch < NCHUNK; ++ch) acc += g_part[ch][b][400 + lane];
        m[lane] = acc;
    }
    __syncwarp();

    for (int p = lane; p < 400; p += 32) {
        float acc = 0.f;
        #pragma unroll
        for (int ch = 0; ch < NCHUNK; ++ch) acc += g_part[ch][b][p];
        int i = p / 20, j = p % 20;
        S[i][j] = (acc - m[i] * m[j] * (1.0f / TT)) * (1.0f / (TT - 1));
    }
    for (int idx = lane; idx < 400; idx += 32) {
        int i = idx / 20, j = idx % 20;
        U[i][j] = (i == j) ? 1.f : 0.f;
    }
    __syncwarp();

    for (int sweep = 0; sweep < NSWEEP; ++sweep) {
        for (int r = 0; r < 19; ++r) {
            if (lane < 10) {
                int p = (lane == 0) ? 0 : 1 + ((lane - 1 + r) % 19);
                int q = 1 + ((18 - lane + r) % 19);
                float app = S[p][p], aqq = S[q][q], apq = S[p][q];
                float c = 1.f, s = 0.f;
                if (fabsf(apq) > 1e-12f) {
                    float tau = __fdividef(aqq - app, 2.f * apq);
                    float t = copysignf(__fdividef(1.f, fabsf(tau) + __fsqrt_rn(1.f + tau * tau)), tau);
                    c = rsqrtf(1.f + t * t);
                    s = t * c;
                }
                cs[lane] = c; sn[lane] = s; pa[lane] = p; qa[lane] = q;
            }
            __syncwarp();
            #pragma unroll
            for (int it = 0; it < 7; ++it) {
                int idx = lane + it * 32;
                if (idx < 200) {
                    int pr = idx / 20, k = idx - pr * 20;
                    int p = pa[pr], q = qa[pr];
                    float c = cs[pr], s = sn[pr];
                    float akp = S[k][p], akq = S[k][q];
                    S[k][p] = c * akp - s * akq;
                    S[k][q] = s * akp + c * akq;
                    float ukp = U[k][p], ukq = U[k][q];
                    U[k][p] = c * ukp - s * ukq;
                    U[k][q] = s * ukp + c * ukq;
                }
            }
            __syncwarp();
            #pragma unroll
            for (int it = 0; it < 7; ++it) {
                int idx = lane + it * 32;
                if (idx < 200) {
                    int pr = idx / 20, k = idx - pr * 20;
                    int p = pa[pr], q = qa[pr];
                    float c = cs[pr], s = sn[pr];
                    float apk = S[p][k], aqk = S[q][k];
                    S[p][k] = c * apk - s * aqk;
                    S[q][k] = s * apk + c * aqk;
                }
            }
            __syncwarp();
        }
    }

    if (lane < 20) lw[lane] = logf(fmaxf(S[lane][lane], 1e-4f));
    __syncwarp();

    float o0 = 0.f, o1 = 0.f, o2 = 0.f, o3 = 0.f;
    const float SQ2 = 1.41421356237309515f;
    for (int p = lane; p < NPAIR; p += 32) {
        int i = 0, rem = p;
        while (rem >= 20 - i) { rem -= 20 - i; ++i; }
        int j = i + rem;
        float L = 0.f;
        #pragma unroll
        for (int mm = 0; mm < 20; ++mm) L += U[i][mm] * lw[mm] * U[j][mm];
        float z = L * ((i == j) ? 1.f : SQ2);
        o0 += z * clf_w[0 * NPAIR + p];
        o1 += z * clf_w[1 * NPAIR + p];
        o2 += z * clf_w[2 * NPAIR + p];
        o3 += z * clf_w[3 * NPAIR + p];
    }
    #pragma unroll
    for (int off = 16; off; off >>= 1) {
        o0 += __shfl_down_sync(0xffffffffu, o0, off);
        o1 += __shfl_down_sync(0xffffffffu, o1, off);
        o2 += __shfl_down_sync(0xffffffffu, o2, off);
        o3 += __shfl_down_sync(0xffffffffu, o3, off);
    }
    if (lane == 0) {
        out[b * 4 + 0] = o0 + clf_b[0];
        out[b * 4 + 1] = o1 + clf_b[1];
        out[b * 4 + 2] = o2 + clf_b[2];
        out[b * 4 + 3] = o3 + clf_b[3];
    }
}

// ---------------------------------------------------------------------------
extern "C" void kernel_launch(void* const* d_in, const int* in_sizes, int n_in,
                              void* d_out, int out_size) {
    const float* x       = (const float*)d_in[0];
    const float* conv1_w = (const float*)d_in[1];
    const float* conv2_w = (const float*)d_in[3];
    const float* W_bimap = (const float*)d_in[5];
    const float* clf_w   = (const float*)d_in[6];
    const float* clf_b   = (const float*)d_in[7];
    float* out = (float*)d_out;

    size_t smem_bytes = (size_t)(NCH * XS_STRIDE + 20 * YS_STRIDE + 2560 + 224) * sizeof(float);
    cudaFuncSetAttribute(conv_cov_kernel,
                         cudaFuncAttributeMaxDynamicSharedMemorySize,
                         (int)smem_bytes);

    prep_kernel<<<10, 256>>>(conv2_w, W_bimap);
    conv_cov_kernel<<<dim3(NCHUNK, BB), 128, smem_bytes>>>(x, conv1_w);
    eig_kernel<<<BB, 32>>>(clf_w, clf_b, out);
}